// round 4
// baseline (speedup 1.0000x reference)
#include <cuda_runtime.h>
#include <cstddef>

// Problem constants (fixed shapes)
#define N_ROWS 14400      // bs*Q = 16*900
#define N_CLS  91
#define N_TGT  4096
#define T_OUT  4096

#define TPB        128
#define TGT_PER_TH 4
#define TILE_T     (TPB * TGT_PER_TH)   // 512 targets per block
#define TILE_R     32                   // rows per block

// Scratch (no allocations allowed in kernel_launch)
__device__ float  g_cc[N_ROWS * N_CLS];   // 2*(pos-neg) + 2, 5.24 MB
__device__ float4 g_rxyxy[N_ROWS];
__device__ float  g_rarea[N_ROWS];
__device__ float4 g_txyxy[N_TGT];
__device__ float  g_tarea[N_TGT];

// ---------------------------------------------------------------------------
// Fused prep: class-cost table (pre-scaled: 2*(pos-neg)+2) + box conversion.
// ---------------------------------------------------------------------------
__global__ void prep_kernel(const float* __restrict__ logits,
                            const float* __restrict__ pboxes,
                            const float* __restrict__ tboxes) {
    int i = blockIdx.x * blockDim.x + threadIdx.x;
    if (i < N_ROWS * N_CLS) {
        float x = logits[i];
        float p = 1.0f / (1.0f + expf(-x));
        float om = 1.0f - p;
        float pos = 0.25f * om * om * (-logf(p + 1e-8f));
        float neg = 0.75f * p * p * (-log1pf(-p + 1e-8f));
        g_cc[i] = 2.0f * (pos - neg) + 2.0f;
    }
    if (i < N_ROWS) {
        float4 b = ((const float4*)pboxes)[i];
        float x0 = b.x - 0.5f * b.z, y0 = b.y - 0.5f * b.w;
        float x1 = b.x + 0.5f * b.z, y1 = b.y + 0.5f * b.w;
        g_rxyxy[i] = make_float4(x0, y0, x1, y1);
        g_rarea[i] = (x1 - x0) * (y1 - y0);
    }
    if (i < N_TGT) {
        float4 b = ((const float4*)tboxes)[i];
        float x0 = b.x - 0.5f * b.z, y0 = b.y - 0.5f * b.w;
        float x1 = b.x + 0.5f * b.z, y1 = b.y + 0.5f * b.w;
        g_txyxy[i] = make_float4(x0, y0, x1, y1);
        g_tarea[i] = (x1 - x0) * (y1 - y0);
    }
}

__device__ __forceinline__ float rcp_fast(float x) {
    float r;
    asm("rcp.approx.f32 %0, %1;" : "=f"(r) : "f"(x));
    return r;
}

// ---------------------------------------------------------------------------
// Main: block = 512 targets x 32 rows. 128 threads, 4 targets/thread.
// Row loop fully unrolled -> all LDS/STG offsets become immediates; cc gather
// is a single LDS per pair. Enclosing box folded through the min/max identity
// (saves 4 FMNMX/pair on the alu pipe).
// ---------------------------------------------------------------------------
__global__ void __launch_bounds__(TPB)
cost_kernel_main(const float* __restrict__ pboxes,
                 const float* __restrict__ tboxes,
                 const int*   __restrict__ tids,
                 float*       __restrict__ out)
{
    __shared__ float4 s_row[TILE_R][3];        // [0]=xyxy [1]=(area,cx,cy,w) [2].x=h
    __shared__ float  s_cc[TILE_R * N_CLS];    // class-cost tile, unpadded pitch 91

    const int n0 = blockIdx.y * TILE_R;
    const int t0 = blockIdx.x * TILE_T + threadIdx.x * TGT_PER_TH;

    // Stage 32 rows of box data: thread t < 32 handles row t.
    if (threadIdx.x < TILE_R) {
        int n = n0 + threadIdx.x;
        float4 x = g_rxyxy[n];
        float4 p = ((const float4*)pboxes)[n];
        float  ar = g_rarea[n];
        s_row[threadIdx.x][0] = x;
        s_row[threadIdx.x][1] = make_float4(ar, p.x, p.y, p.z);
        s_row[threadIdx.x][2] = make_float4(p.w, 0.f, 0.f, 0.f);
    }

    // Stage cc tile: straight contiguous float4 copy (32*91*4 B = 728 float4,
    // 16B-aligned since n0*91*4 is a multiple of 16 when n0%4==0; n0=32*by ok).
    {
        const float4* __restrict__ src = (const float4*)(g_cc + n0 * N_CLS);
        float4* __restrict__ dst = (float4*)s_cc;
        #pragma unroll
        for (int q = 0; q < (TILE_R * N_CLS) / 4 / TPB + 1; ++q) {
            int idx = q * TPB + threadIdx.x;
            if (idx < (TILE_R * N_CLS) / 4) dst[idx] = src[idx];
        }
    }

    // Per-thread target data (4 targets) in registers
    float4 tx[TGT_PER_TH];   // xyxy
    float  ta[TGT_PER_TH];   // area
    float4 tc[TGT_PER_TH];   // cxcywh
    int    cls[TGT_PER_TH];
    #pragma unroll
    for (int j = 0; j < TGT_PER_TH; ++j) {
        int t = t0 + j;
        tx[j]  = g_txyxy[t];
        ta[j]  = g_tarea[t];
        tc[j]  = ((const float4*)tboxes)[t];
        cls[j] = tids[t];
    }

    __syncthreads();

    float* __restrict__ outp = out + (size_t)n0 * T_OUT + t0;

    #pragma unroll
    for (int r = 0; r < TILE_R; ++r) {
        const float4 ra = s_row[r][0];     // x0 y0 x1 y1
        const float4 rb = s_row[r][1];     // area cx cy w
        const float  rh = s_row[r][2].x;   // h
        const float* __restrict__ ccrow = s_cc + r * N_CLS;

        float c[TGT_PER_TH];
        #pragma unroll
        for (int j = 0; j < TGT_PER_TH; ++j) {
            const float ccv = ccrow[cls[j]];             // 2*cc + 2 (LDS, imm offset)

            // L1 on cxcywh
            float l1 = fabsf(rb.y - tc[j].x) + fabsf(rb.z - tc[j].y)
                     + fabsf(rb.w - tc[j].z) + fabsf(rh   - tc[j].w);

            // intersection
            float ltx = fmaxf(ra.x, tx[j].x), lty = fmaxf(ra.y, tx[j].y);
            float rbx = fminf(ra.z, tx[j].z), rby = fminf(ra.w, tx[j].w);
            float iwu = rbx - ltx, ihu = rby - lty;
            float iw = fmaxf(iwu, 0.0f), ih = fmaxf(ihu, 0.0f);
            float inter = iw * ih;
            float uni = (rb.x + ta[j]) - inter;

            // enclosing box via identity: ew = (rw + tw) - iwu, eh = (rh + th) - ihu
            float ew = (rb.w + tc[j].z) - iwu;
            float eh = (rh   + tc[j].w) - ihu;
            float ae = ew * eh;

            // s = inter/uni + uni/ae ; cost = 5*l1 + (2cc+2) - 2*s
            float s = fmaf(uni, rcp_fast(ae), inter * rcp_fast(uni));
            c[j] = fmaf(5.0f, l1, fmaf(-2.0f, s, ccv));
        }
        *(float4*)(outp + (size_t)r * T_OUT) =
            make_float4(c[0], c[1], c[2], c[3]);
    }
}

// ---------------------------------------------------------------------------
// Launch
// ---------------------------------------------------------------------------
extern "C" void kernel_launch(void* const* d_in, const int* in_sizes, int n_in,
                              void* d_out, int out_size) {
    const float* logits = (const float*)d_in[0];   // [16,900,91]
    const float* pboxes = (const float*)d_in[1];   // [16,900,4]
    const int*   tids   = (const int*)  d_in[2];   // [4096]
    const float* tboxes = (const float*)d_in[3];   // [4096,4]
    float*       out    = (float*)d_out;           // [16,900,4096]

    {
        int total = N_ROWS * N_CLS;
        prep_kernel<<<(total + 255) / 256, 256>>>(logits, pboxes, tboxes);
    }
    {
        dim3 grid(T_OUT / TILE_T, N_ROWS / TILE_R);
        cost_kernel_main<<<grid, TPB>>>(pboxes, tboxes, tids, out);
    }
}

// round 5
// speedup vs baseline: 1.1813x; 1.1813x over previous
#include <cuda_runtime.h>
#include <cstddef>

// Problem constants (fixed shapes)
#define N_ROWS 14400      // bs*Q = 16*900
#define N_CLS  91
#define N_TGT  4096
#define T_OUT  4096

#define TPB        256
#define TGT_PER_TH 4
#define TILE_T     (TPB * TGT_PER_TH)   // 1024 targets per block
#define TILE_R     32                   // rows per block

// Scratch (no allocations allowed in kernel_launch)
__device__ float  g_cc[N_ROWS * N_CLS];   // 2*(pos-neg) + 2, 5.24 MB
__device__ float4 g_rxyxy[N_ROWS];
__device__ float  g_rarea[N_ROWS];
__device__ float4 g_txyxy[N_TGT];
__device__ float  g_tarea[N_TGT];

// ---------------------------------------------------------------------------
// Fused prep: class-cost table (pre-scaled: 2*(pos-neg)+2) + box conversion.
// ---------------------------------------------------------------------------
__global__ void prep_kernel(const float* __restrict__ logits,
                            const float* __restrict__ pboxes,
                            const float* __restrict__ tboxes) {
    int i = blockIdx.x * blockDim.x + threadIdx.x;
    if (i < N_ROWS * N_CLS) {
        float x = logits[i];
        float p = 1.0f / (1.0f + expf(-x));
        float om = 1.0f - p;
        float pos = 0.25f * om * om * (-logf(p + 1e-8f));
        float neg = 0.75f * p * p * (-log1pf(-p + 1e-8f));
        g_cc[i] = 2.0f * (pos - neg) + 2.0f;
    }
    if (i < N_ROWS) {
        float4 b = ((const float4*)pboxes)[i];
        float x0 = b.x - 0.5f * b.z, y0 = b.y - 0.5f * b.w;
        float x1 = b.x + 0.5f * b.z, y1 = b.y + 0.5f * b.w;
        g_rxyxy[i] = make_float4(x0, y0, x1, y1);
        g_rarea[i] = (x1 - x0) * (y1 - y0);
    }
    if (i < N_TGT) {
        float4 b = ((const float4*)tboxes)[i];
        float x0 = b.x - 0.5f * b.z, y0 = b.y - 0.5f * b.w;
        float x1 = b.x + 0.5f * b.z, y1 = b.y + 0.5f * b.w;
        g_txyxy[i] = make_float4(x0, y0, x1, y1);
        g_tarea[i] = (x1 - x0) * (y1 - y0);
    }
}

__device__ __forceinline__ float rcp_fast(float x) {
    float r;
    asm("rcp.approx.f32 %0, %1;" : "=f"(r) : "f"(x));
    return r;
}

// ---------------------------------------------------------------------------
// Main: block = 1024 targets x 32 rows. 256 threads, 4 targets/thread.
// Partial unroll (4) keeps regs ~64 for occupancy; cc gather is one LDS/pair;
// enclosing box via the min/max identity (alu-pipe diet from R4 retained).
// ---------------------------------------------------------------------------
__global__ void __launch_bounds__(TPB)
cost_kernel_main(const float* __restrict__ pboxes,
                 const float* __restrict__ tboxes,
                 const int*   __restrict__ tids,
                 float*       __restrict__ out)
{
    __shared__ float4 s_row[TILE_R][3];        // [0]=xyxy [1]=(area,cx,cy,w) [2].x=h
    __shared__ float  s_cc[TILE_R * N_CLS];    // class-cost tile, pitch 91

    const int n0 = blockIdx.y * TILE_R;
    const int t0 = blockIdx.x * TILE_T + threadIdx.x * TGT_PER_TH;

    // Stage 32 rows of box data: thread t < 32 handles row t.
    if (threadIdx.x < TILE_R) {
        int n = n0 + threadIdx.x;
        float4 x = g_rxyxy[n];
        float4 p = ((const float4*)pboxes)[n];
        float  ar = g_rarea[n];
        s_row[threadIdx.x][0] = x;
        s_row[threadIdx.x][1] = make_float4(ar, p.x, p.y, p.z);
        s_row[threadIdx.x][2] = make_float4(p.w, 0.f, 0.f, 0.f);
    }

    // Stage cc tile: contiguous float4 copy (728 float4, 16B-aligned:
    // n0*91*4 % 16 == 0 since n0 is a multiple of 32).
    {
        const float4* __restrict__ src = (const float4*)(g_cc + n0 * N_CLS);
        float4* __restrict__ dst = (float4*)s_cc;
        #pragma unroll
        for (int q = 0; q < 3; ++q) {
            int idx = q * TPB + threadIdx.x;
            if (idx < (TILE_R * N_CLS) / 4) dst[idx] = src[idx];
        }
    }

    // Per-thread target data (4 targets) in registers
    float4 tx[TGT_PER_TH];   // xyxy
    float  ta[TGT_PER_TH];   // area
    float4 tc[TGT_PER_TH];   // cxcywh
    int    cls[TGT_PER_TH];
    #pragma unroll
    for (int j = 0; j < TGT_PER_TH; ++j) {
        int t = t0 + j;
        tx[j]  = g_txyxy[t];
        ta[j]  = g_tarea[t];
        tc[j]  = ((const float4*)tboxes)[t];
        cls[j] = tids[t];
    }

    __syncthreads();

    float* __restrict__ outp = out + (size_t)n0 * T_OUT + t0;

    #pragma unroll 4
    for (int r = 0; r < TILE_R; ++r) {
        const float4 ra = s_row[r][0];     // x0 y0 x1 y1
        const float4 rb = s_row[r][1];     // area cx cy w
        const float  rh = s_row[r][2].x;   // h
        const float* __restrict__ ccrow = s_cc + r * N_CLS;

        float c[TGT_PER_TH];
        #pragma unroll
        for (int j = 0; j < TGT_PER_TH; ++j) {
            const float ccv = ccrow[cls[j]];             // 2*cc + 2 (LDS)

            // L1 on cxcywh
            float l1 = fabsf(rb.y - tc[j].x) + fabsf(rb.z - tc[j].y)
                     + fabsf(rb.w - tc[j].z) + fabsf(rh   - tc[j].w);

            // intersection
            float ltx = fmaxf(ra.x, tx[j].x), lty = fmaxf(ra.y, tx[j].y);
            float rbx = fminf(ra.z, tx[j].z), rby = fminf(ra.w, tx[j].w);
            float iwu = rbx - ltx, ihu = rby - lty;
            float iw = fmaxf(iwu, 0.0f), ih = fmaxf(ihu, 0.0f);
            float inter = iw * ih;
            float uni = (rb.x + ta[j]) - inter;

            // enclosing box identity: ew = (rw + tw) - iwu, eh = (rh + th) - ihu
            float ew = (rb.w + tc[j].z) - iwu;
            float eh = (rh   + tc[j].w) - ihu;
            float ae = ew * eh;

            // s = inter/uni + uni/ae ; cost = 5*l1 + (2cc+2) - 2*s
            float s = fmaf(uni, rcp_fast(ae), inter * rcp_fast(uni));
            c[j] = fmaf(5.0f, l1, fmaf(-2.0f, s, ccv));
        }
        *(float4*)(outp + (size_t)r * T_OUT) =
            make_float4(c[0], c[1], c[2], c[3]);
    }
}

// ---------------------------------------------------------------------------
// Launch
// ---------------------------------------------------------------------------
extern "C" void kernel_launch(void* const* d_in, const int* in_sizes, int n_in,
                              void* d_out, int out_size) {
    const float* logits = (const float*)d_in[0];   // [16,900,91]
    const float* pboxes = (const float*)d_in[1];   // [16,900,4]
    const int*   tids   = (const int*)  d_in[2];   // [4096]
    const float* tboxes = (const float*)d_in[3];   // [4096,4]
    float*       out    = (float*)d_out;           // [16,900,4096]

    {
        int total = N_ROWS * N_CLS;
        prep_kernel<<<(total + 255) / 256, 256>>>(logits, pboxes, tboxes);
    }
    {
        dim3 grid(T_OUT / TILE_T, N_ROWS / TILE_R);
        cost_kernel_main<<<grid, TPB>>>(pboxes, tboxes, tids, out);
    }
}

// round 6
// speedup vs baseline: 1.2328x; 1.0436x over previous
#include <cuda_runtime.h>
#include <cstddef>

// Problem constants (fixed shapes)
#define N_ROWS 14400      // bs*Q = 16*900
#define N_CLS  91
#define N_TGT  4096
#define T_OUT  4096

#define TPB        256
#define TGT_PER_TH 2                    // one packed f32x2 lane-pair
#define TILE_T     (TPB * TGT_PER_TH)   // 512 targets per block
#define TILE_R     32                   // rows per block

// Scratch (no allocations allowed in kernel_launch)
__device__ float  g_cc[N_ROWS * N_CLS];   // 2*(pos-neg) + 2, 5.24 MB
__device__ float4 g_rxyxy[N_ROWS];
__device__ float  g_rarea[N_ROWS];
__device__ float4 g_txyxy[N_TGT];
__device__ float  g_tarea[N_TGT];

// ---------------------------------------------------------------------------
// Packed f32x2 helpers (sm_100+: add/mul/fma.rn.f32x2)
// ---------------------------------------------------------------------------
struct F2 { unsigned long long u; };

__device__ __forceinline__ F2 pack2(float lo, float hi) {
    F2 r; asm("mov.b64 %0, {%1, %2};" : "=l"(r.u) : "f"(lo), "f"(hi)); return r;
}
__device__ __forceinline__ void unpack2(F2 a, float& lo, float& hi) {
    asm("mov.b64 {%0, %1}, %2;" : "=f"(lo), "=f"(hi) : "l"(a.u));
}
__device__ __forceinline__ F2 add2(F2 a, F2 b) {
    F2 r; asm("add.rn.f32x2 %0, %1, %2;" : "=l"(r.u) : "l"(a.u), "l"(b.u)); return r;
}
__device__ __forceinline__ F2 mul2(F2 a, F2 b) {
    F2 r; asm("mul.rn.f32x2 %0, %1, %2;" : "=l"(r.u) : "l"(a.u), "l"(b.u)); return r;
}
__device__ __forceinline__ F2 fma2(F2 a, F2 b, F2 c) {
    F2 r; asm("fma.rn.f32x2 %0, %1, %2, %3;"
              : "=l"(r.u) : "l"(a.u), "l"(b.u), "l"(c.u)); return r;
}
__device__ __forceinline__ float rcp_fast(float x) {
    float r; asm("rcp.approx.f32 %0, %1;" : "=f"(r) : "f"(x)); return r;
}

// ---------------------------------------------------------------------------
// Fused prep: class-cost table (pre-scaled: 2*(pos-neg)+2) + box conversion.
// ---------------------------------------------------------------------------
__global__ void prep_kernel(const float* __restrict__ logits,
                            const float* __restrict__ pboxes,
                            const float* __restrict__ tboxes) {
    int i = blockIdx.x * blockDim.x + threadIdx.x;
    if (i < N_ROWS * N_CLS) {
        float x = logits[i];
        float p = 1.0f / (1.0f + expf(-x));
        float om = 1.0f - p;
        float pos = 0.25f * om * om * (-logf(p + 1e-8f));
        float neg = 0.75f * p * p * (-log1pf(-p + 1e-8f));
        g_cc[i] = 2.0f * (pos - neg) + 2.0f;
    }
    if (i < N_ROWS) {
        float4 b = ((const float4*)pboxes)[i];
        float x0 = b.x - 0.5f * b.z, y0 = b.y - 0.5f * b.w;
        float x1 = b.x + 0.5f * b.z, y1 = b.y + 0.5f * b.w;
        g_rxyxy[i] = make_float4(x0, y0, x1, y1);
        g_rarea[i] = (x1 - x0) * (y1 - y0);
    }
    if (i < N_TGT) {
        float4 b = ((const float4*)tboxes)[i];
        float x0 = b.x - 0.5f * b.z, y0 = b.y - 0.5f * b.w;
        float x1 = b.x + 0.5f * b.z, y1 = b.y + 0.5f * b.w;
        g_txyxy[i] = make_float4(x0, y0, x1, y1);
        g_tarea[i] = (x1 - x0) * (y1 - y0);
    }
}

// ---------------------------------------------------------------------------
// Main: block = 512 targets x 32 rows. 256 threads, 2 targets/thread packed
// into one f32x2 lane. Row-side values duplicated in shared so packed ops
// consume them directly; target-side constants pre-negated so all subs are
// add2/fma2. min/max scalar; clamps via FADD.SAT.
// ---------------------------------------------------------------------------
__global__ void __launch_bounds__(TPB)
cost_kernel_main(const float* __restrict__ pboxes,
                 const float* __restrict__ tboxes,
                 const int*   __restrict__ tids,
                 float*       __restrict__ out)
{
    __shared__ float4 s_row[TILE_R][4];
    // rec0: x0 y0 x1 y1
    // rec1: 5cx 5cx 5cy 5cy
    // rec2: w  w  h  h
    // rec3: ar ar 0 0
    __shared__ float s_cc[TILE_R * N_CLS];

    const int n0 = blockIdx.y * TILE_R;
    const int t0 = blockIdx.x * TILE_T + threadIdx.x * TGT_PER_TH;

    // Stage row records (thread t < 32 handles row t)
    if (threadIdx.x < TILE_R) {
        int n = n0 + threadIdx.x;
        float4 x = g_rxyxy[n];
        float4 p = ((const float4*)pboxes)[n];
        float  ar = g_rarea[n];
        s_row[threadIdx.x][0] = x;
        s_row[threadIdx.x][1] = make_float4(5.f*p.x, 5.f*p.x, 5.f*p.y, 5.f*p.y);
        s_row[threadIdx.x][2] = make_float4(p.z, p.z, p.w, p.w);
        s_row[threadIdx.x][3] = make_float4(ar, ar, 0.f, 0.f);
    }

    // Stage cc tile (contiguous float4 copy; 728 float4, 16B-aligned)
    {
        const float4* __restrict__ src = (const float4*)(g_cc + n0 * N_CLS);
        float4* __restrict__ dst = (float4*)s_cc;
        #pragma unroll
        for (int q = 0; q < 3; ++q) {
            int idx = q * TPB + threadIdx.x;
            if (idx < (TILE_R * N_CLS) / 4) dst[idx] = src[idx];
        }
    }

    // Target state: 2 targets per thread
    const float4 xa = g_txyxy[t0];
    const float4 xb = g_txyxy[t0 + 1];
    const float4 ca = ((const float4*)tboxes)[t0];
    const float4 cb = ((const float4*)tboxes)[t0 + 1];
    const int cls0 = tids[t0];
    const int cls1 = tids[t0 + 1];

    // scalar minmax operands (xy pre-negated for the min(-a,-b) form)
    const float ntax = -xa.x, ntay = -xa.y, taz = xa.z, taw = xa.w;
    const float ntbx = -xb.x, ntby = -xb.y, tbz = xb.z, tbw = xb.w;

    // packed target constants (negated where consumed as subtrahend)
    const F2 TCX5N = pack2(-5.f*ca.x, -5.f*cb.x);
    const F2 TCY5N = pack2(-5.f*ca.y, -5.f*cb.y);
    const F2 TCWN  = pack2(-ca.z, -cb.z);
    const F2 TCHN  = pack2(-ca.w, -cb.w);
    const F2 TA01  = pack2(g_tarea[t0], g_tarea[t0 + 1]);
    const F2 NEG1  = pack2(-1.0f, -1.0f);
    const F2 NEG2  = pack2(-2.0f, -2.0f);

    __syncthreads();

    float* __restrict__ outp = out + (size_t)n0 * T_OUT + t0;

    #pragma unroll 4
    for (int r = 0; r < TILE_R; ++r) {
        const float4 r0 = s_row[r][0];   // xyxy (scalar use)
        const float4 r1 = s_row[r][1];   // {5cx,5cx,5cy,5cy}
        const float4 r2 = s_row[r][2];   // {w,w,h,h}
        const float4 r3 = s_row[r][3];   // {ar,ar,-,-}

        const F2 CX5 = pack2(r1.x, r1.y);
        const F2 CY5 = pack2(r1.z, r1.w);
        const F2 W2  = pack2(r2.x, r2.y);
        const F2 H2  = pack2(r2.z, r2.w);
        const F2 AR2 = pack2(r3.x, r3.y);

        // L1 deltas (packed): 5*(cx - tcx), etc.
        const F2 DX = add2(CX5, TCX5N);
        const F2 DY = add2(CY5, TCY5N);
        const F2 DW = add2(W2,  TCWN);   // unscaled (w - tw)
        const F2 DH = add2(H2,  TCHN);
        // sums for enclosing box: w + tw = fma2(TCWN, -1, W2)
        const F2 RWTW = fma2(TCWN, NEG1, W2);
        const F2 RHTH = fma2(TCHN, NEG1, H2);
        const F2 ARTA = add2(AR2, TA01);

        float dx0, dx1, dy0, dy1, dw0, dw1, dh0, dh1;
        unpack2(DX, dx0, dx1); unpack2(DY, dy0, dy1);
        unpack2(DW, dw0, dw1); unpack2(DH, dh0, dh1);
        const float a10 = fabsf(dx0) + fabsf(dy0);   // 5*(|dcx|+|dcy|)
        const float a11 = fabsf(dx1) + fabsf(dy1);
        const float a20 = fabsf(dw0) + fabsf(dh0);   // |dw|+|dh|
        const float a21 = fabsf(dw1) + fabsf(dh1);

        // scalar intersection minmax (neg modifiers fold into FMNMX)
        const float ltxn0 = fminf(-r0.x, ntax), ltyn0 = fminf(-r0.y, ntay);
        const float rbx0  = fminf( r0.z, taz),  rby0  = fminf( r0.w, taw);
        const float ltxn1 = fminf(-r0.x, ntbx), ltyn1 = fminf(-r0.y, ntby);
        const float rbx1  = fminf( r0.z, tbz),  rby1  = fminf( r0.w, tbw);

        const float iwu0 = rbx0 + ltxn0, ihu0 = rby0 + ltyn0;
        const float iwu1 = rbx1 + ltxn1, ihu1 = rby1 + ltyn1;
        const float iw0 = __saturatef(rbx0 + ltxn0);  // == max(iwu,0), iwu<=1
        const float ih0 = __saturatef(rby0 + ltyn0);
        const float iw1 = __saturatef(rbx1 + ltxn1);
        const float ih1 = __saturatef(rby1 + ltyn1);

        const F2 IWU = pack2(iwu0, iwu1);
        const F2 IHU = pack2(ihu0, ihu1);
        const F2 IW  = pack2(iw0, iw1);
        const F2 IH  = pack2(ih0, ih1);

        const F2 INTER = mul2(IW, IH);
        const F2 UNI   = fma2(INTER, NEG1, ARTA);   // ar+ta - inter
        const F2 EW    = fma2(IWU, NEG1, RWTW);     // (w+tw) - iwu
        const F2 EH    = fma2(IHU, NEG1, RHTH);
        const F2 AE    = mul2(EW, EH);

        float u0, u1, e0, e1;
        unpack2(UNI, u0, u1); unpack2(AE, e0, e1);
        const F2 RCPU = pack2(rcp_fast(u0), rcp_fast(u1));
        const F2 RCPA = pack2(rcp_fast(e0), rcp_fast(e1));

        const F2 T = mul2(INTER, RCPU);
        const F2 S = fma2(UNI, RCPA, T);            // inter/uni + uni/ae

        const float* __restrict__ ccrow = s_cc + r * N_CLS;
        const F2 CCV = pack2(ccrow[cls0], ccrow[cls1]);   // 2cc+2
        const F2 C   = fma2(S, NEG2, CCV);                // ccv - 2s

        float c0b, c1b;
        unpack2(C, c0b, c1b);
        const float c0 = a10 + fmaf(5.0f, a20, c0b);
        const float c1 = a11 + fmaf(5.0f, a21, c1b);

        *(float2*)(outp + (size_t)r * T_OUT) = make_float2(c0, c1);
    }
}

// ---------------------------------------------------------------------------
// Launch
// ---------------------------------------------------------------------------
extern "C" void kernel_launch(void* const* d_in, const int* in_sizes, int n_in,
                              void* d_out, int out_size) {
    const float* logits = (const float*)d_in[0];   // [16,900,91]
    const float* pboxes = (const float*)d_in[1];   // [16,900,4]
    const int*   tids   = (const int*)  d_in[2];   // [4096]
    const float* tboxes = (const float*)d_in[3];   // [4096,4]
    float*       out    = (float*)d_out;           // [16,900,4096]

    {
        int total = N_ROWS * N_CLS;
        prep_kernel<<<(total + 255) / 256, 256>>>(logits, pboxes, tboxes);
    }
    {
        dim3 grid(T_OUT / TILE_T, N_ROWS / TILE_R);
        cost_kernel_main<<<grid, TPB>>>(pboxes, tboxes, tids, out);
    }
}

// round 7
// speedup vs baseline: 1.2532x; 1.0166x over previous
#include <cuda_runtime.h>
#include <cstddef>

// Problem constants (fixed shapes)
#define N_ROWS 14400      // bs*Q = 16*900
#define N_CLS  91
#define N_TGT  4096
#define T_OUT  4096

#define TPB        256
#define TGT_PER_TH 2                    // one packed f32x2 lane-pair
#define TILE_T     (TPB * TGT_PER_TH)   // 512 targets per block
#define TILE_R     32                   // rows per block

// Scratch (no allocations allowed in kernel_launch)
__device__ float  g_cc[N_ROWS * N_CLS];   // 2*(pos-neg) + 2, 5.24 MB
__device__ float4 g_rxyxy[N_ROWS];
__device__ float  g_rarea[N_ROWS];
__device__ float4 g_txyxy[N_TGT];

// ---------------------------------------------------------------------------
// Packed f32x2 helpers (sm_100+: add/mul/fma.rn.f32x2)
// ---------------------------------------------------------------------------
struct F2 { unsigned long long u; };

__device__ __forceinline__ F2 pack2(float lo, float hi) {
    F2 r; asm("mov.b64 %0, {%1, %2};" : "=l"(r.u) : "f"(lo), "f"(hi)); return r;
}
__device__ __forceinline__ void unpack2(F2 a, float& lo, float& hi) {
    asm("mov.b64 {%0, %1}, %2;" : "=f"(lo), "=f"(hi) : "l"(a.u));
}
__device__ __forceinline__ F2 add2(F2 a, F2 b) {
    F2 r; asm("add.rn.f32x2 %0, %1, %2;" : "=l"(r.u) : "l"(a.u), "l"(b.u)); return r;
}
__device__ __forceinline__ F2 mul2(F2 a, F2 b) {
    F2 r; asm("mul.rn.f32x2 %0, %1, %2;" : "=l"(r.u) : "l"(a.u), "l"(b.u)); return r;
}
__device__ __forceinline__ F2 fma2(F2 a, F2 b, F2 c) {
    F2 r; asm("fma.rn.f32x2 %0, %1, %2, %3;"
              : "=l"(r.u) : "l"(a.u), "l"(b.u), "l"(c.u)); return r;
}
__device__ __forceinline__ float rcp_fast(float x) {
    float r; asm("rcp.approx.f32 %0, %1;" : "=f"(r) : "f"(x)); return r;
}

// ---------------------------------------------------------------------------
// Fused prep: class-cost table (pre-scaled: 2*(pos-neg)+2) + box conversion.
// ---------------------------------------------------------------------------
__global__ void prep_kernel(const float* __restrict__ logits,
                            const float* __restrict__ pboxes,
                            const float* __restrict__ tboxes) {
    int i = blockIdx.x * blockDim.x + threadIdx.x;
    if (i < N_ROWS * N_CLS) {
        float x = logits[i];
        float p = 1.0f / (1.0f + expf(-x));
        float om = 1.0f - p;
        float pos = 0.25f * om * om * (-logf(p + 1e-8f));
        float neg = 0.75f * p * p * (-log1pf(-p + 1e-8f));
        g_cc[i] = 2.0f * (pos - neg) + 2.0f;
    }
    if (i < N_ROWS) {
        float4 b = ((const float4*)pboxes)[i];
        float x0 = b.x - 0.5f * b.z, y0 = b.y - 0.5f * b.w;
        float x1 = b.x + 0.5f * b.z, y1 = b.y + 0.5f * b.w;
        g_rxyxy[i] = make_float4(x0, y0, x1, y1);
        g_rarea[i] = (x1 - x0) * (y1 - y0);
    }
    if (i < N_TGT) {
        float4 b = ((const float4*)tboxes)[i];
        float x0 = b.x - 0.5f * b.z, y0 = b.y - 0.5f * b.w;
        float x1 = b.x + 0.5f * b.z, y1 = b.y + 0.5f * b.w;
        g_txyxy[i] = make_float4(x0, y0, x1, y1);
    }
}

// ---------------------------------------------------------------------------
// Main: block = 512 targets x 32 rows. 256 threads, 2 targets/thread packed
// into one f32x2 lane. Row-side packed duplicates live in shared as 64-bit
// words -> LDS.64 straight into aligned register pairs (no pack MOVs).
// Target area folded as TCWN*TCHN inside an fma2. Forced 5 blocks/SM.
// ---------------------------------------------------------------------------
__global__ void __launch_bounds__(TPB, 5)
cost_kernel_main(const float* __restrict__ pboxes,
                 const float* __restrict__ tboxes,
                 const int*   __restrict__ tids,
                 float*       __restrict__ out)
{
    __shared__ float4 s_rxy[TILE_R];                      // xyxy
    __shared__ unsigned long long s_rp[TILE_R][5];        // {5cx,5cx}{5cy,5cy}{w,w}{h,h}{ar,ar}
    __shared__ float s_cc[TILE_R * N_CLS];

    const int n0 = blockIdx.y * TILE_R;
    const int t0 = blockIdx.x * TILE_T + threadIdx.x * TGT_PER_TH;

    // Stage row records (thread t < 32 handles row t)
    if (threadIdx.x < TILE_R) {
        int n = n0 + threadIdx.x;
        float4 p = ((const float4*)pboxes)[n];
        float  ar = g_rarea[n];
        s_rxy[threadIdx.x] = g_rxyxy[n];
        s_rp[threadIdx.x][0] = pack2(5.f*p.x, 5.f*p.x).u;
        s_rp[threadIdx.x][1] = pack2(5.f*p.y, 5.f*p.y).u;
        s_rp[threadIdx.x][2] = pack2(p.z, p.z).u;
        s_rp[threadIdx.x][3] = pack2(p.w, p.w).u;
        s_rp[threadIdx.x][4] = pack2(ar, ar).u;
    }

    // Stage cc tile (contiguous float4 copy; 728 float4, 16B-aligned)
    {
        const float4* __restrict__ src = (const float4*)(g_cc + n0 * N_CLS);
        float4* __restrict__ dst = (float4*)s_cc;
        #pragma unroll
        for (int q = 0; q < 3; ++q) {
            int idx = q * TPB + threadIdx.x;
            if (idx < (TILE_R * N_CLS) / 4) dst[idx] = src[idx];
        }
    }

    // Target state: 2 targets per thread (kept minimal for regs <= 51)
    const float4 xa = g_txyxy[t0];          // xyxy target 0
    const float4 xb = g_txyxy[t0 + 1];      // xyxy target 1
    const float4 ca = ((const float4*)tboxes)[t0];
    const float4 cb = ((const float4*)tboxes)[t0 + 1];
    const int cls0 = tids[t0];
    const int cls1 = tids[t0 + 1];

    // packed target constants (negated where consumed as subtrahend)
    const F2 TCX5N = pack2(-5.f*ca.x, -5.f*cb.x);
    const F2 TCY5N = pack2(-5.f*ca.y, -5.f*cb.y);
    const F2 TCWN  = pack2(-ca.z, -cb.z);
    const F2 TCHN  = pack2(-ca.w, -cb.w);
    const F2 NEG1  = pack2(-1.0f, -1.0f);
    const F2 NEG2  = pack2(-2.0f, -2.0f);

    __syncthreads();

    float* __restrict__ outp = out + (size_t)n0 * T_OUT + t0;

    #pragma unroll 4
    for (int r = 0; r < TILE_R; ++r) {
        const float4 r0 = s_rxy[r];          // x0 y0 x1 y1 (scalar minmax)
        const F2 CX5 = { s_rp[r][0] };
        const F2 CY5 = { s_rp[r][1] };
        const F2 W2  = { s_rp[r][2] };
        const F2 H2  = { s_rp[r][3] };
        const F2 AR2 = { s_rp[r][4] };

        // L1 deltas (packed)
        const F2 DX = add2(CX5, TCX5N);      // 5*(cx - tcx)
        const F2 DY = add2(CY5, TCY5N);
        const F2 DW = add2(W2,  TCWN);       // (w - tw)
        const F2 DH = add2(H2,  TCHN);
        // enclosing sums + union base
        const F2 RWTW = fma2(TCWN, NEG1, W2);      // w + tw
        const F2 RHTH = fma2(TCHN, NEG1, H2);      // h + th
        const F2 ARTA = fma2(TCWN, TCHN, AR2);     // ar + tw*th

        float dx0, dx1, dy0, dy1, dw0, dw1, dh0, dh1;
        unpack2(DX, dx0, dx1); unpack2(DY, dy0, dy1);
        unpack2(DW, dw0, dw1); unpack2(DH, dh0, dh1);
        const float a10 = fabsf(dx0) + fabsf(dy0);   // 5*(|dcx|+|dcy|)
        const float a11 = fabsf(dx1) + fabsf(dy1);
        const float a20 = fabsf(dw0) + fabsf(dh0);   // |dw|+|dh|
        const float a21 = fabsf(dw1) + fabsf(dh1);

        // scalar intersection minmax (neg folds into FMNMX modifiers)
        const float ltxn0 = fminf(-r0.x, -xa.x), ltyn0 = fminf(-r0.y, -xa.y);
        const float rbx0  = fminf( r0.z,  xa.z), rby0  = fminf( r0.w,  xa.w);
        const float ltxn1 = fminf(-r0.x, -xb.x), ltyn1 = fminf(-r0.y, -xb.y);
        const float rbx1  = fminf( r0.z,  xb.z), rby1  = fminf( r0.w,  xb.w);

        const float iwu0 = rbx0 + ltxn0, ihu0 = rby0 + ltyn0;
        const float iwu1 = rbx1 + ltxn1, ihu1 = rby1 + ltyn1;
        const float iw0 = __saturatef(iwu0);   // == max(iwu,0); iwu < 1 always
        const float ih0 = __saturatef(ihu0);
        const float iw1 = __saturatef(iwu1);
        const float ih1 = __saturatef(ihu1);

        const F2 IWU = pack2(iwu0, iwu1);
        const F2 IHU = pack2(ihu0, ihu1);
        const F2 IW  = pack2(iw0, iw1);
        const F2 IH  = pack2(ih0, ih1);

        const F2 INTER = mul2(IW, IH);
        const F2 UNI   = fma2(INTER, NEG1, ARTA);   // ar+ta - inter
        const F2 EW    = fma2(IWU, NEG1, RWTW);     // (w+tw) - iwu
        const F2 EH    = fma2(IHU, NEG1, RHTH);
        const F2 AE    = mul2(EW, EH);

        float u0, u1, e0, e1;
        unpack2(UNI, u0, u1); unpack2(AE, e0, e1);
        const F2 RCPU = pack2(rcp_fast(u0), rcp_fast(u1));
        const F2 RCPA = pack2(rcp_fast(e0), rcp_fast(e1));

        const F2 T = mul2(INTER, RCPU);
        const F2 S = fma2(UNI, RCPA, T);            // inter/uni + uni/ae

        const F2 CCV = pack2(s_cc[r * N_CLS + cls0],
                             s_cc[r * N_CLS + cls1]);     // 2cc+2
        const F2 C   = fma2(S, NEG2, CCV);                // ccv - 2s

        float c0b, c1b;
        unpack2(C, c0b, c1b);
        const float c0 = a10 + fmaf(5.0f, a20, c0b);
        const float c1 = a11 + fmaf(5.0f, a21, c1b);

        *(float2*)(outp + (size_t)r * T_OUT) = make_float2(c0, c1);
    }
}

// ---------------------------------------------------------------------------
// Launch
// ---------------------------------------------------------------------------
extern "C" void kernel_launch(void* const* d_in, const int* in_sizes, int n_in,
                              void* d_out, int out_size) {
    const float* logits = (const float*)d_in[0];   // [16,900,91]
    const float* pboxes = (const float*)d_in[1];   // [16,900,4]
    const int*   tids   = (const int*)  d_in[2];   // [4096]
    const float* tboxes = (const float*)d_in[3];   // [4096,4]
    float*       out    = (float*)d_out;           // [16,900,4096]

    {
        int total = N_ROWS * N_CLS;
        prep_kernel<<<(total + 255) / 256, 256>>>(logits, pboxes, tboxes);
    }
    {
        dim3 grid(T_OUT / TILE_T, N_ROWS / TILE_R);
        cost_kernel_main<<<grid, TPB>>>(pboxes, tboxes, tids, out);
    }
}

// round 8
// speedup vs baseline: 1.3927x; 1.1113x over previous
#include <cuda_runtime.h>
#include <cstddef>

// Problem constants (fixed shapes)
#define N_ROWS 14400      // bs*Q = 16*900
#define N_CLS  91
#define N_TGT  4096
#define T_OUT  4096

#define TPB        256
#define TGT_PER_TH 2                    // one packed f32x2 lane-pair
#define TILE_T     (TPB * TGT_PER_TH)   // 512 targets per block
#define TILE_R     32                   // rows per block

// Scratch (no allocations allowed in kernel_launch)
__device__ float  g_cc[N_ROWS * N_CLS];   // 2*(pos-neg) + 2, 5.24 MB
__device__ float4 g_rxyxy[N_ROWS];
__device__ float  g_rarea[N_ROWS];
__device__ float4 g_txyxy[N_TGT];

// ---------------------------------------------------------------------------
// Packed f32x2 helpers (sm_100+: add/mul/fma.rn.f32x2)
// ---------------------------------------------------------------------------
struct F2 { unsigned long long u; };

__device__ __forceinline__ F2 pack2(float lo, float hi) {
    F2 r; asm("mov.b64 %0, {%1, %2};" : "=l"(r.u) : "f"(lo), "f"(hi)); return r;
}
__device__ __forceinline__ void unpack2(F2 a, float& lo, float& hi) {
    asm("mov.b64 {%0, %1}, %2;" : "=f"(lo), "=f"(hi) : "l"(a.u));
}
__device__ __forceinline__ F2 add2(F2 a, F2 b) {
    F2 r; asm("add.rn.f32x2 %0, %1, %2;" : "=l"(r.u) : "l"(a.u), "l"(b.u)); return r;
}
__device__ __forceinline__ F2 mul2(F2 a, F2 b) {
    F2 r; asm("mul.rn.f32x2 %0, %1, %2;" : "=l"(r.u) : "l"(a.u), "l"(b.u)); return r;
}
__device__ __forceinline__ F2 fma2(F2 a, F2 b, F2 c) {
    F2 r; asm("fma.rn.f32x2 %0, %1, %2, %3;"
              : "=l"(r.u) : "l"(a.u), "l"(b.u), "l"(c.u)); return r;
}
__device__ __forceinline__ float rcp_fast(float x) {
    float r; asm("rcp.approx.f32 %0, %1;" : "=f"(r) : "f"(x)); return r;
}

// ---------------------------------------------------------------------------
// Fused prep: class-cost table (pre-scaled: 2*(pos-neg)+2) + box conversion.
// Fast intrinsics: logits ~ N(0,1) => p in [~5e-3, ~0.995]; __logf/__expf
// error ~2^-21 rel -> worst-case ~1e-4 absolute on the class term, far under
// the 1e-3 output tolerance.
// ---------------------------------------------------------------------------
__global__ void prep_kernel(const float* __restrict__ logits,
                            const float* __restrict__ pboxes,
                            const float* __restrict__ tboxes) {
    int i = blockIdx.x * blockDim.x + threadIdx.x;
    if (i < N_ROWS * N_CLS) {
        float x = logits[i];
        float p = rcp_fast(1.0f + __expf(-x));
        float om = 1.0f - p;
        float pos = 0.25f * om * om * (-__logf(p  + 1e-8f));
        float neg = 0.75f * p  * p  * (-__logf(om + 1e-8f));
        g_cc[i] = 2.0f * (pos - neg) + 2.0f;
    }
    if (i < N_ROWS) {
        float4 b = ((const float4*)pboxes)[i];
        float x0 = b.x - 0.5f * b.z, y0 = b.y - 0.5f * b.w;
        float x1 = b.x + 0.5f * b.z, y1 = b.y + 0.5f * b.w;
        g_rxyxy[i] = make_float4(x0, y0, x1, y1);
        g_rarea[i] = (x1 - x0) * (y1 - y0);
    }
    if (i < N_TGT) {
        float4 b = ((const float4*)tboxes)[i];
        float x0 = b.x - 0.5f * b.z, y0 = b.y - 0.5f * b.w;
        float x1 = b.x + 0.5f * b.z, y1 = b.y + 0.5f * b.w;
        g_txyxy[i] = make_float4(x0, y0, x1, y1);
    }
}

// ---------------------------------------------------------------------------
// Main: block = 512 targets x 32 rows. 256 threads, 2 targets/thread packed
// into one f32x2 lane. Single-reciprocal GIoU:
//   inter/uni + uni/ae = (inter*ae + uni^2) * rcp(uni*ae)
// -> 2 MUFU per packed pair instead of 4.
// ---------------------------------------------------------------------------
__global__ void __launch_bounds__(TPB, 5)
cost_kernel_main(const float* __restrict__ pboxes,
                 const float* __restrict__ tboxes,
                 const int*   __restrict__ tids,
                 float*       __restrict__ out)
{
    __shared__ float4 s_rxy[TILE_R];                      // xyxy
    __shared__ unsigned long long s_rp[TILE_R][5];        // {5cx,5cx}{5cy,5cy}{w,w}{h,h}{ar,ar}
    __shared__ float s_cc[TILE_R * N_CLS];

    const int n0 = blockIdx.y * TILE_R;
    const int t0 = blockIdx.x * TILE_T + threadIdx.x * TGT_PER_TH;

    // Stage row records (thread t < 32 handles row t)
    if (threadIdx.x < TILE_R) {
        int n = n0 + threadIdx.x;
        float4 p = ((const float4*)pboxes)[n];
        float  ar = g_rarea[n];
        s_rxy[threadIdx.x] = g_rxyxy[n];
        s_rp[threadIdx.x][0] = pack2(5.f*p.x, 5.f*p.x).u;
        s_rp[threadIdx.x][1] = pack2(5.f*p.y, 5.f*p.y).u;
        s_rp[threadIdx.x][2] = pack2(p.z, p.z).u;
        s_rp[threadIdx.x][3] = pack2(p.w, p.w).u;
        s_rp[threadIdx.x][4] = pack2(ar, ar).u;
    }

    // Stage cc tile (contiguous float4 copy; 728 float4, 16B-aligned)
    {
        const float4* __restrict__ src = (const float4*)(g_cc + n0 * N_CLS);
        float4* __restrict__ dst = (float4*)s_cc;
        #pragma unroll
        for (int q = 0; q < 3; ++q) {
            int idx = q * TPB + threadIdx.x;
            if (idx < (TILE_R * N_CLS) / 4) dst[idx] = src[idx];
        }
    }

    // Target state: 2 targets per thread
    const float4 xa = g_txyxy[t0];          // xyxy target 0
    const float4 xb = g_txyxy[t0 + 1];      // xyxy target 1
    const float4 ca = ((const float4*)tboxes)[t0];
    const float4 cb = ((const float4*)tboxes)[t0 + 1];
    const int cls0 = tids[t0];
    const int cls1 = tids[t0 + 1];

    // packed target constants (negated where consumed as subtrahend)
    const F2 TCX5N = pack2(-5.f*ca.x, -5.f*cb.x);
    const F2 TCY5N = pack2(-5.f*ca.y, -5.f*cb.y);
    const F2 TCWN  = pack2(-ca.z, -cb.z);
    const F2 TCHN  = pack2(-ca.w, -cb.w);
    const F2 NEG1  = pack2(-1.0f, -1.0f);
    const F2 NEG2  = pack2(-2.0f, -2.0f);

    __syncthreads();

    float* __restrict__ outp = out + (size_t)n0 * T_OUT + t0;

    #pragma unroll 4
    for (int r = 0; r < TILE_R; ++r) {
        const float4 r0 = s_rxy[r];          // x0 y0 x1 y1 (scalar minmax)
        const F2 CX5 = { s_rp[r][0] };
        const F2 CY5 = { s_rp[r][1] };
        const F2 W2  = { s_rp[r][2] };
        const F2 H2  = { s_rp[r][3] };
        const F2 AR2 = { s_rp[r][4] };

        // L1 deltas (packed)
        const F2 DX = add2(CX5, TCX5N);      // 5*(cx - tcx)
        const F2 DY = add2(CY5, TCY5N);
        const F2 DW = add2(W2,  TCWN);       // (w - tw)
        const F2 DH = add2(H2,  TCHN);
        // enclosing sums + union base
        const F2 RWTW = fma2(TCWN, NEG1, W2);      // w + tw
        const F2 RHTH = fma2(TCHN, NEG1, H2);      // h + th
        const F2 ARTA = fma2(TCWN, TCHN, AR2);     // ar + tw*th

        float dx0, dx1, dy0, dy1, dw0, dw1, dh0, dh1;
        unpack2(DX, dx0, dx1); unpack2(DY, dy0, dy1);
        unpack2(DW, dw0, dw1); unpack2(DH, dh0, dh1);
        const float a10 = fabsf(dx0) + fabsf(dy0);   // 5*(|dcx|+|dcy|)
        const float a11 = fabsf(dx1) + fabsf(dy1);
        const float a20 = fabsf(dw0) + fabsf(dh0);   // |dw|+|dh|
        const float a21 = fabsf(dw1) + fabsf(dh1);

        // scalar intersection minmax (neg folds into FMNMX modifiers)
        const float ltxn0 = fminf(-r0.x, -xa.x), ltyn0 = fminf(-r0.y, -xa.y);
        const float rbx0  = fminf( r0.z,  xa.z), rby0  = fminf( r0.w,  xa.w);
        const float ltxn1 = fminf(-r0.x, -xb.x), ltyn1 = fminf(-r0.y, -xb.y);
        const float rbx1  = fminf( r0.z,  xb.z), rby1  = fminf( r0.w,  xb.w);

        const float iwu0 = rbx0 + ltxn0, ihu0 = rby0 + ltyn0;
        const float iwu1 = rbx1 + ltxn1, ihu1 = rby1 + ltyn1;
        const float iw0 = __saturatef(iwu0);   // == max(iwu,0); iwu < 1 always
        const float ih0 = __saturatef(ihu0);
        const float iw1 = __saturatef(iwu1);
        const float ih1 = __saturatef(ihu1);

        const F2 IWU = pack2(iwu0, iwu1);
        const F2 IHU = pack2(ihu0, ihu1);
        const F2 IW  = pack2(iw0, iw1);
        const F2 IH  = pack2(ih0, ih1);

        const F2 INTER = mul2(IW, IH);
        const F2 UNI   = fma2(INTER, NEG1, ARTA);   // ar+ta - inter
        const F2 EW    = fma2(IWU, NEG1, RWTW);     // (w+tw) - iwu
        const F2 EH    = fma2(IHU, NEG1, RHTH);
        const F2 AE    = mul2(EW, EH);

        // single-rcp GIoU: s = (inter*ae + uni^2) / (uni*ae)
        const F2 DEN = mul2(UNI, AE);
        float d0, d1;
        unpack2(DEN, d0, d1);
        const F2 RCPD = pack2(rcp_fast(d0), rcp_fast(d1));
        const F2 NUM  = fma2(UNI, UNI, mul2(INTER, AE));
        const F2 S    = mul2(NUM, RCPD);

        const F2 CCV = pack2(s_cc[r * N_CLS + cls0],
                             s_cc[r * N_CLS + cls1]);     // 2cc+2
        const F2 C   = fma2(S, NEG2, CCV);                // ccv - 2s

        float c0b, c1b;
        unpack2(C, c0b, c1b);
        const float c0 = a10 + fmaf(5.0f, a20, c0b);
        const float c1 = a11 + fmaf(5.0f, a21, c1b);

        *(float2*)(outp + (size_t)r * T_OUT) = make_float2(c0, c1);
    }
}

// ---------------------------------------------------------------------------
// Launch
// ---------------------------------------------------------------------------
extern "C" void kernel_launch(void* const* d_in, const int* in_sizes, int n_in,
                              void* d_out, int out_size) {
    const float* logits = (const float*)d_in[0];   // [16,900,91]
    const float* pboxes = (const float*)d_in[1];   // [16,900,4]
    const int*   tids   = (const int*)  d_in[2];   // [4096]
    const float* tboxes = (const float*)d_in[3];   // [4096,4]
    float*       out    = (float*)d_out;           // [16,900,4096]

    {
        int total = N_ROWS * N_CLS;
        prep_kernel<<<(total + 255) / 256, 256>>>(logits, pboxes, tboxes);
    }
    {
        dim3 grid(T_OUT / TILE_T, N_ROWS / TILE_R);
        cost_kernel_main<<<grid, TPB>>>(pboxes, tboxes, tids, out);
    }
}